// round 16
// baseline (speedup 1.0000x reference)
#include <cuda_runtime.h>
#include <cuda_fp16.h>
#include <cstdint>

// Problem constants
#define NB   8
#define LSEQ 1024
#define EMB  1024
#define NH   16
#define HD   64

// Scratch (allocation-free rule: device globals) — fp16 intermediates
__device__ __half g_Qp[NB * LSEQ * EMB];   // pre-scaled by log2(e)/32
__device__ __half g_Kp[NB * LSEQ * EMB];
__device__ __half g_Vp[NB * LSEQ * EMB];
__device__ __half g_AO[NB * LSEQ * EMB];
__device__ __half g_Wt[EMB * EMB];          // fp16 Wo

// ---------------------------------------------------------------------------
__device__ __forceinline__ uint32_t pack2(float lo, float hi) {
    __half2 h = __floats2half2_rn(lo, hi);
    return *reinterpret_cast<uint32_t*>(&h);
}
__device__ __forceinline__ uint32_t h2exp2w(uint32_t x) {
    uint32_t y;
    asm("ex2.approx.f16x2 %0, %1;" : "=r"(y) : "r"(x));
    return y;
}
__device__ __forceinline__ uint32_t smem_u32(const void* p) {
    uint32_t a;
    asm("{ .reg .u64 t; cvta.to.shared.u64 t, %1; cvt.u32.u64 %0, t; }"
        : "=r"(a) : "l"(p));
    return a;
}
__device__ __forceinline__ void cp16(uint32_t s, const void* g) {
    asm volatile("cp.async.cg.shared.global [%0], [%1], 16;" :: "r"(s), "l"(g));
}
#define CP_COMMIT() asm volatile("cp.async.commit_group;" ::: "memory")
#define CP_WAIT(n)  asm volatile("cp.async.wait_group %0;" :: "n"(n) : "memory")

// D += A*B, m16n8k16 fp16 inputs, fp32 accum.
__device__ __forceinline__ void mma16(float* d, const uint32_t* a, const uint32_t* b) {
    asm("mma.sync.aligned.m16n8k16.row.col.f32.f16.f16.f32 "
        "{%0,%1,%2,%3}, {%4,%5,%6,%7}, {%8,%9}, {%0,%1,%2,%3};"
        : "+f"(d[0]), "+f"(d[1]), "+f"(d[2]), "+f"(d[3])
        : "r"(a[0]), "r"(a[1]), "r"(a[2]), "r"(a[3]), "r"(b[0]), "r"(b[1]));
}
__device__ __forceinline__ void ldsm4(uint32_t* r, uint32_t addr) {
    asm volatile("ldmatrix.sync.aligned.m8n8.x4.shared.b16 {%0,%1,%2,%3}, [%4];"
        : "=r"(r[0]), "=r"(r[1]), "=r"(r[2]), "=r"(r[3]) : "r"(addr));
}
__device__ __forceinline__ void ldsm4t(uint32_t* r, uint32_t addr) {
    asm volatile("ldmatrix.sync.aligned.m8n8.x4.trans.shared.b16 {%0,%1,%2,%3}, [%4];"
        : "=r"(r[0]), "=r"(r[1]), "=r"(r[2]), "=r"(r[3]) : "r"(addr));
}
// lane word-offsets for ldmatrix addressing (row pad = 36 words)
__device__ __forceinline__ int laneA_off(int i) {
    return ((i & 7) + ((i >> 3) & 1) * 8) * 36 + ((i >> 4) & 1) * 4;
}
__device__ __forceinline__ int laneB_off(int i) {
    return ((i & 7) + ((i >> 4) & 1) * 8) * 36 + ((i >> 3) & 1) * 4;
}

// ===========================================================================
// Fused front-end. blockIdx.y: 0=Q (pre-scaled), 1=K, 2=V projection (64-row
// tiles, 2048 blocks each), 3=Wo->fp16 (1024 blocks).
// Proj: C[64 x 64] = X[64 x 64] * W[64 x 64]^T.
// smem (words): As 64*36, Bs 64*36.
// ===========================================================================
__global__ __launch_bounds__(256) void proj_all(
    const float* __restrict__ q, const float* __restrict__ k,
    const float* __restrict__ v,
    const float* __restrict__ Wq, const float* __restrict__ Wk,
    const float* __restrict__ Wv,
    __half* __restrict__ Qp, __half* __restrict__ Kp, __half* __restrict__ Vp,
    const float* __restrict__ Wo, __half* __restrict__ Wt)
{
    const int t = threadIdx.x;
    if (blockIdx.y == 3) {
        if (blockIdx.x >= 1024) return;
        int i = blockIdx.x * 256 + t;
        float4 w = reinterpret_cast<const float4*>(Wo)[i];
        uint2 u = make_uint2(pack2(w.x, w.y), pack2(w.z, w.w));
        *reinterpret_cast<uint2*>(reinterpret_cast<uint32_t*>(Wt) + i * 2) = u;
        return;
    }

    extern __shared__ uint32_t sm[];
    uint32_t* As = sm;            // [64][36] words
    uint32_t* Bs = sm + 64 * 36;

    const float* A = (blockIdx.y == 0) ? q : (blockIdx.y == 1) ? k : v;
    const float* B = (blockIdx.y == 0) ? Wq : (blockIdx.y == 1) ? Wk : Wv;
    __half* C = (blockIdx.y == 0) ? Qp : (blockIdx.y == 1) ? Kp : Vp;
    const float scale = (blockIdx.y == 0) ? (0.03125f * 1.44269504088896f) : 1.f;

    const int lane = t & 31, wid = t >> 5;
    const int wm = wid & 3, wn = wid >> 2;   // 4 m-warps x 2 n-warps
    const int g = lane >> 2, tg = lane & 3;

    A += (long long)blockIdx.x * 64 * 64;

#pragma unroll
    for (int i = 0; i < 4; ++i) {
        int s = t + i * 256, r = s >> 4, c4 = (s & 15) << 2;
        float4 vv = *reinterpret_cast<const float4*>(A + (long long)r * 64 + c4);
        uint2 u = make_uint2(pack2(vv.x, vv.y), pack2(vv.z, vv.w));
        *reinterpret_cast<uint2*>(&As[r * 36 + (c4 >> 1)]) = u;
    }
#pragma unroll
    for (int i = 0; i < 4; ++i) {
        int s = t + i * 256, r = s >> 4, c4 = (s & 15) << 2;
        float4 vv = *reinterpret_cast<const float4*>(B + (long long)r * 64 + c4);
        uint2 u = make_uint2(pack2(vv.x, vv.y), pack2(vv.z, vv.w));
        *reinterpret_cast<uint2*>(&Bs[r * 36 + (c4 >> 1)]) = u;
    }
    __syncthreads();

    float acc[4][4];
#pragma unroll
    for (int j = 0; j < 4; ++j)
#pragma unroll
        for (int e = 0; e < 4; ++e) acc[j][e] = 0.f;

#pragma unroll
    for (int ks = 0; ks < 4; ++ks) {
        int kb = ks * 8;
        uint32_t af[4];
        int row = wm * 16 + g;
        af[0] = As[row * 36 + kb + tg];
        af[1] = As[(row + 8) * 36 + kb + tg];
        af[2] = As[row * 36 + kb + tg + 4];
        af[3] = As[(row + 8) * 36 + kb + tg + 4];
#pragma unroll
        for (int nt = 0; nt < 4; ++nt) {
            int col = wn * 32 + nt * 8 + g;
            uint32_t bf[2];
            bf[0] = Bs[col * 36 + kb + tg];
            bf[1] = Bs[col * 36 + kb + tg + 4];
            mma16(acc[nt], af, bf);
        }
    }

    uint32_t* Cw = reinterpret_cast<uint32_t*>(C) + (long long)blockIdx.x * 64 * 32;
    const int row = wm * 16 + g;
#pragma unroll
    for (int nt = 0; nt < 4; ++nt) {
        int colw = (wn * 32 + nt * 8 + 2 * tg) >> 1;
        Cw[row * 32 + colw]       = pack2(acc[nt][0] * scale, acc[nt][1] * scale);
        Cw[(row + 8) * 32 + colw] = pack2(acc[nt][2] * scale, acc[nt][3] * scale);
    }
}

// ===========================================================================
// Big GEMM: out[8192 x 1024] = AO * Wt^T, fp16 in, fp32 out. 128x128 tile,
// k-chunk 64, cp.async TRIPLE buffer (single sync per chunk), ldmatrix,
// 2 CTAs/SM. smem words: As 3*4608 at 0; Bs 3*4608 at 13824. 110592 B.
// ===========================================================================
__global__ __launch_bounds__(256, 2) void gemm_big(
    const __half* __restrict__ A, const __half* __restrict__ B,
    float* __restrict__ C)
{
    extern __shared__ uint32_t sm[];
    const uint32_t sbase = smem_u32(sm);

    const int t = threadIdx.x, lane = t & 31, wid = t >> 5;
    const int wm = wid & 1, wn = wid >> 1;
    const int g = lane >> 2, tg = lane & 3;
    const int lA = laneA_off(lane), lB = laneB_off(lane);

    A += (long long)blockIdx.x * 128 * 1024;
    B += (long long)blockIdx.y * 128 * 1024;
    C += (long long)blockIdx.x * 128 * 1024 + (long long)blockIdx.y * 128;

    float acc[4][4][4];
#pragma unroll
    for (int i = 0; i < 4; ++i)
#pragma unroll
        for (int j = 0; j < 4; ++j)
#pragma unroll
            for (int e = 0; e < 4; ++e) acc[i][j][e] = 0.f;

#pragma unroll
    for (int i = 0; i < 4; ++i) {
        int s = t + i * 256, r = s >> 3, ch = s & 7;
        cp16(sbase + (r * 36 + ch * 4) * 4, A + (long long)r * 1024 + ch * 8);
        cp16(sbase + (13824 + r * 36 + ch * 4) * 4, B + (long long)r * 1024 + ch * 8);
    }
    CP_COMMIT();

    for (int ck = 0; ck < 16; ++ck) {
        if (ck < 15) {
            int kc = (ck + 1) * 64, b = (ck + 1) % 3;
#pragma unroll
            for (int i = 0; i < 4; ++i) {
                int s = t + i * 256, r = s >> 3, ch = s & 7;
                cp16(sbase + (b * 4608 + r * 36 + ch * 4) * 4,
                     A + (long long)r * 1024 + kc + ch * 8);
                cp16(sbase + (13824 + b * 4608 + r * 36 + ch * 4) * 4,
                     B + (long long)r * 1024 + kc + ch * 8);
            }
            CP_COMMIT();
            CP_WAIT(1);
        } else {
            CP_WAIT(0);
        }
        __syncthreads();   // single barrier per chunk (triple buffer)

        const int rb = ck % 3;
        const uint32_t Aad = sbase + (rb * 4608 + wm * 64 * 36 + lA) * 4;
        const uint32_t Bad = sbase + (13824 + rb * 4608 + wn * 32 * 36 + lB) * 4;
#pragma unroll
        for (int ks = 0; ks < 4; ++ks) {
            uint32_t af[4][4];
#pragma unroll
            for (int mt = 0; mt < 4; ++mt)
                ldsm4(af[mt], Aad + (mt * 16 * 36 + ks * 8) * 4);
            uint32_t bfp[2][4];
#pragma unroll
            for (int ntp = 0; ntp < 2; ++ntp)
                ldsm4(bfp[ntp], Bad + (ntp * 16 * 36 + ks * 8) * 4);
#pragma unroll
            for (int mt = 0; mt < 4; ++mt)
#pragma unroll
                for (int ntp = 0; ntp < 2; ++ntp) {
                    mma16(acc[mt][2 * ntp],     af[mt], &bfp[ntp][0]);
                    mma16(acc[mt][2 * ntp + 1], af[mt], &bfp[ntp][2]);
                }
        }
    }

#pragma unroll
    for (int mt = 0; mt < 4; ++mt) {
        int row = wm * 64 + mt * 16 + g;
#pragma unroll
        for (int nt = 0; nt < 4; ++nt) {
            int col = wn * 32 + nt * 8 + 2 * tg;
            *reinterpret_cast<float2*>(C + (long long)row * 1024 + col) =
                make_float2(acc[mt][nt][0], acc[mt][nt][1]);
            *reinterpret_cast<float2*>(C + (long long)(row + 8) * 1024 + col) =
                make_float2(acc[mt][nt][2], acc[mt][nt][3]);
        }
    }
}

// ===========================================================================
// Flash attention, fp16 mma m16n8k16, BK=64 TRIPLE-buffered, 2 CTAs/SM.
// 8 warps x 16 q-rows. Q pre-scaled by log2(e)/32 -> exp path is pack+ex2
// only. S/exp/PV fused per 16-col slice. smem words: Qs 0 (4608),
// K bufs 4608 + b*2304 (x3), V bufs 11520 + b*2304 (x3). 73728 B.
// ===========================================================================
__global__ __launch_bounds__(256, 2) void attn_tc(
    const __half* __restrict__ Qp, const __half* __restrict__ Kp,
    const __half* __restrict__ Vp, __half* __restrict__ AO)
{
    extern __shared__ uint32_t sm[];
    const uint32_t sbase = smem_u32(sm);

    const int t = threadIdx.x, lane = t & 31, wid = t >> 5;
    const int g = lane >> 2, tg = lane & 3;
    const int lA = laneA_off(lane), lB = laneB_off(lane);
    const int qt = blockIdx.x, h = blockIdx.y, n = blockIdx.z;

    const long long base = ((long long)n << 20) + h * 64;          // halves
    const __half* Qb = Qp + base + (long long)(qt * 128) * 1024;

    // prefetch Q [128r x 32w] + K/V tile0 into buf0 (group 0)
#pragma unroll
    for (int i = 0; i < 4; ++i) {
        int s = t + i * 256, r = s >> 3, ch = s & 7;
        cp16(sbase + (r * 36 + ch * 4) * 4, Qb + (long long)r * 1024 + ch * 8);
    }
#pragma unroll
    for (int i = 0; i < 2; ++i) {
        int s = t + i * 256, r = s >> 3, ch = s & 7;
        cp16(sbase + (4608 + r * 36 + ch * 4) * 4, Kp + base + (long long)r * 1024 + ch * 8);
        cp16(sbase + (11520 + r * 36 + ch * 4) * 4, Vp + base + (long long)r * 1024 + ch * 8);
    }
    CP_COMMIT();

    float Of[8][4];
    float Osum[4] = {0.f, 0.f, 0.f, 0.f};
#pragma unroll
    for (int dtl = 0; dtl < 8; ++dtl)
#pragma unroll
        for (int e = 0; e < 4; ++e) Of[dtl][e] = 0.f;

    uint32_t Qa[4][4];                               // hoisted Q A-frags
    const uint32_t ONES2[2] = {0x3C003C00u, 0x3C003C00u};

    for (int kt = 0; kt < 16; ++kt) {
        if (kt < 15) {
            int b = (kt + 1) % 3;
            const __half* Kb = Kp + base + (long long)((kt + 1) * 64) * 1024;
            const __half* Vb = Vp + base + (long long)((kt + 1) * 64) * 1024;
#pragma unroll
            for (int i = 0; i < 2; ++i) {
                int s = t + i * 256, r = s >> 3, ch = s & 7;
                cp16(sbase + (4608 + b * 2304 + r * 36 + ch * 4) * 4,
                     Kb + (long long)r * 1024 + ch * 8);
                cp16(sbase + (11520 + b * 2304 + r * 36 + ch * 4) * 4,
                     Vb + (long long)r * 1024 + ch * 8);
            }
            CP_COMMIT();
            CP_WAIT(1);
        } else {
            CP_WAIT(0);
        }
        __syncthreads();   // single barrier per tile (triple buffer)

        if (kt == 0) {
            uint32_t Qad = sbase + (wid * 16 * 36 + lA) * 4;
#pragma unroll
            for (int ds = 0; ds < 4; ++ds)
                ldsm4(Qa[ds], Qad + ds * 8 * 4);
        }

        const int rb = kt % 3;
        const uint32_t Kad = sbase + (4608 + rb * 2304 + lB) * 4;
        const uint32_t Vad = sbase + (11520 + rb * 2304 + lA) * 4;

        // ---- fused per 16-col slice: S -> exp -> lsum-mma -> PV ----
#pragma unroll
        for (int ntp = 0; ntp < 4; ++ntp) {
            float Sa[4] = {0.f, 0.f, 0.f, 0.f};
            float Sb[4] = {0.f, 0.f, 0.f, 0.f};
#pragma unroll
            for (int ds = 0; ds < 4; ++ds) {
                uint32_t bf[4];
                ldsm4(bf, Kad + (ntp * 16 * 36 + ds * 8) * 4);
                mma16(Sa, Qa[ds], &bf[0]);
                mma16(Sb, Qa[ds], &bf[2]);
            }
            uint32_t pa[4];
            pa[0] = h2exp2w(pack2(Sa[0], Sa[1]));   // Q pre-scaled: no FMUL
            pa[1] = h2exp2w(pack2(Sa[2], Sa[3]));
            pa[2] = h2exp2w(pack2(Sb[0], Sb[1]));
            pa[3] = h2exp2w(pack2(Sb[2], Sb[3]));
            mma16(Osum, pa, ONES2);   // row-sums of P
#pragma unroll
            for (int dp = 0; dp < 4; ++dp) {
                uint32_t bf[4];
                ldsm4t(bf, Vad + (ntp * 16 * 36 + dp * 8) * 4);
                mma16(Of[2 * dp],     pa, &bf[0]);
                mma16(Of[2 * dp + 1], pa, &bf[2]);
            }
        }
    }

    // ---- epilogue: normalize (Osum c0 = row g, c2 = row g+8), write ----
    float inv0 = 1.f / Osum[0], inv1 = 1.f / Osum[2];

    const int q0 = qt * 128 + wid * 16 + g;
    uint32_t* Ob0 = reinterpret_cast<uint32_t*>(AO)
                  + (((long long)n * 1024 + q0) * 1024 + h * 64) / 2;
    uint32_t* Ob1 = reinterpret_cast<uint32_t*>(AO)
                  + (((long long)n * 1024 + q0 + 8) * 1024 + h * 64) / 2;
#pragma unroll
    for (int dtl = 0; dtl < 8; ++dtl) {
        int dw = (dtl * 8 + 2 * tg) >> 1;
        Ob0[dw] = pack2(Of[dtl][0] * inv0, Of[dtl][1] * inv0);
        Ob1[dw] = pack2(Of[dtl][2] * inv1, Of[dtl][3] * inv1);
    }
}

// ===========================================================================
extern "C" void kernel_launch(void* const* d_in, const int* in_sizes, int n_in,
                              void* d_out, int out_size)
{
    (void)in_sizes; (void)n_in; (void)out_size;
    const float* key   = (const float*)d_in[0];
    const float* query = (const float*)d_in[1];
    const float* value = (const float*)d_in[2];
    /* d_in[3] = mask — faithfully ignored (reference no-op) */
    const float* Wq = (const float*)d_in[4];
    const float* Wk = (const float*)d_in[5];
    const float* Wv = (const float*)d_in[6];
    const float* Wo = (const float*)d_in[7];
    float* out = (float*)d_out;

    __half *Qp, *Kp, *Vp, *AO, *Wt;
    cudaGetSymbolAddress((void**)&Qp, g_Qp);
    cudaGetSymbolAddress((void**)&Kp, g_Kp);
    cudaGetSymbolAddress((void**)&Vp, g_Vp);
    cudaGetSymbolAddress((void**)&AO, g_AO);
    cudaGetSymbolAddress((void**)&Wt, g_Wt);

    const int smem_proj = (64 * 36 + 64 * 36) * 4;    // 18432
    const int smem_big  = 27648 * 4;                  // 110592
    const int smem_attn = 18432 * 4;                  // 73728
    cudaFuncSetAttribute(proj_all,
        cudaFuncAttributeMaxDynamicSharedMemorySize, smem_proj);
    cudaFuncSetAttribute(gemm_big,
        cudaFuncAttributeMaxDynamicSharedMemorySize, smem_big);
    cudaFuncSetAttribute(attn_tc,
        cudaFuncAttributeMaxDynamicSharedMemorySize, smem_attn);

    dim3 blk(256);

    // Fused projections (y=0..2, 64-row tiles; Q pre-scaled) + Wo->fp16 (y=3)
    proj_all<<<dim3(2048, 4), blk, smem_proj>>>(
        query, key, value, Wq, Wk, Wv, Qp, Kp, Vp, Wo, Wt);

    // Attention: grid (q-tiles=8, heads=16, batch=8)
    attn_tc<<<dim3(8, NH, NB), blk, smem_attn>>>(Qp, Kp, Vp, AO);

    // Output projection: out = AO * Wt^T (fp16 in, fp32 out)
    gemm_big<<<dim3(64, 8), blk, smem_big>>>(AO, Wt, out);
}

// round 17
// speedup vs baseline: 1.7550x; 1.7550x over previous
#include <cuda_runtime.h>
#include <cuda_fp16.h>
#include <cstdint>

// Problem constants
#define NB   8
#define LSEQ 1024
#define EMB  1024
#define NH   16
#define HD   64

// Scratch (allocation-free rule: device globals) — fp16 intermediates
__device__ __half g_Qp[NB * LSEQ * EMB];   // pre-scaled by log2(e)/32
__device__ __half g_Kp[NB * LSEQ * EMB];
__device__ __half g_Vp[NB * LSEQ * EMB];
__device__ __half g_AO[NB * LSEQ * EMB];
__device__ __half g_Wt[EMB * EMB];          // fp16 Wo

// ---------------------------------------------------------------------------
__device__ __forceinline__ uint32_t pack2(float lo, float hi) {
    __half2 h = __floats2half2_rn(lo, hi);
    return *reinterpret_cast<uint32_t*>(&h);
}
__device__ __forceinline__ uint32_t h2exp2w(uint32_t x) {
    uint32_t y;
    asm("ex2.approx.f16x2 %0, %1;" : "=r"(y) : "r"(x));
    return y;
}
__device__ __forceinline__ uint32_t smem_u32(const void* p) {
    uint32_t a;
    asm("{ .reg .u64 t; cvta.to.shared.u64 t, %1; cvt.u32.u64 %0, t; }"
        : "=r"(a) : "l"(p));
    return a;
}
__device__ __forceinline__ void cp16(uint32_t s, const void* g) {
    asm volatile("cp.async.cg.shared.global [%0], [%1], 16;" :: "r"(s), "l"(g));
}
#define CP_COMMIT() asm volatile("cp.async.commit_group;" ::: "memory")
#define CP_WAIT(n)  asm volatile("cp.async.wait_group %0;" :: "n"(n) : "memory")

// D += A*B, m16n8k16 fp16 inputs, fp32 accum.
__device__ __forceinline__ void mma16(float* d, const uint32_t* a, const uint32_t* b) {
    asm("mma.sync.aligned.m16n8k16.row.col.f32.f16.f16.f32 "
        "{%0,%1,%2,%3}, {%4,%5,%6,%7}, {%8,%9}, {%0,%1,%2,%3};"
        : "+f"(d[0]), "+f"(d[1]), "+f"(d[2]), "+f"(d[3])
        : "r"(a[0]), "r"(a[1]), "r"(a[2]), "r"(a[3]), "r"(b[0]), "r"(b[1]));
}
__device__ __forceinline__ void ldsm4(uint32_t* r, uint32_t addr) {
    asm volatile("ldmatrix.sync.aligned.m8n8.x4.shared.b16 {%0,%1,%2,%3}, [%4];"
        : "=r"(r[0]), "=r"(r[1]), "=r"(r[2]), "=r"(r[3]) : "r"(addr));
}
__device__ __forceinline__ void ldsm4t(uint32_t* r, uint32_t addr) {
    asm volatile("ldmatrix.sync.aligned.m8n8.x4.trans.shared.b16 {%0,%1,%2,%3}, [%4];"
        : "=r"(r[0]), "=r"(r[1]), "=r"(r[2]), "=r"(r[3]) : "r"(addr));
}
// lane word-offsets for ldmatrix addressing (row pad = 36 words)
__device__ __forceinline__ int laneA_off(int i) {
    return ((i & 7) + ((i >> 3) & 1) * 8) * 36 + ((i >> 4) & 1) * 4;
}
__device__ __forceinline__ int laneB_off(int i) {
    return ((i & 7) + ((i >> 4) & 1) * 8) * 36 + ((i >> 3) & 1) * 4;
}

// ===========================================================================
// Fused front-end. blockIdx.y: 0=Q (pre-scaled), 1=K, 2=V projection,
// 3=Wo->fp16. Proj: C[128 x 64] = X[128 x 64] * W[64 x 64]^T (R15 tiles).
// ===========================================================================
__global__ __launch_bounds__(256) void proj_all(
    const float* __restrict__ q, const float* __restrict__ k,
    const float* __restrict__ v,
    const float* __restrict__ Wq, const float* __restrict__ Wk,
    const float* __restrict__ Wv,
    __half* __restrict__ Qp, __half* __restrict__ Kp, __half* __restrict__ Vp,
    const float* __restrict__ Wo, __half* __restrict__ Wt)
{
    const int t = threadIdx.x;
    if (blockIdx.y == 3) {
        int i = blockIdx.x * 256 + t;
        float4 w = reinterpret_cast<const float4*>(Wo)[i];
        uint2 u = make_uint2(pack2(w.x, w.y), pack2(w.z, w.w));
        *reinterpret_cast<uint2*>(reinterpret_cast<uint32_t*>(Wt) + i * 2) = u;
        return;
    }

    extern __shared__ uint32_t sm[];
    uint32_t* As = sm;            // [128][36] words
    uint32_t* Bs = sm + 128 * 36;

    const float* A = (blockIdx.y == 0) ? q : (blockIdx.y == 1) ? k : v;
    const float* B = (blockIdx.y == 0) ? Wq : (blockIdx.y == 1) ? Wk : Wv;
    __half* C = (blockIdx.y == 0) ? Qp : (blockIdx.y == 1) ? Kp : Vp;
    const float scale = (blockIdx.y == 0) ? (0.03125f * 1.44269504088896f) : 1.f;

    const int lane = t & 31, wid = t >> 5;
    const int wm = wid & 1, wn = wid >> 1;
    const int g = lane >> 2, tg = lane & 3;

    A += (long long)blockIdx.x * 128 * 64;

#pragma unroll
    for (int i = 0; i < 8; ++i) {
        int s = t + i * 256, r = s >> 4, c4 = (s & 15) << 2;
        float4 vv = *reinterpret_cast<const float4*>(A + (long long)r * 64 + c4);
        uint2 u = make_uint2(pack2(vv.x, vv.y), pack2(vv.z, vv.w));
        *reinterpret_cast<uint2*>(&As[r * 36 + (c4 >> 1)]) = u;
    }
#pragma unroll
    for (int i = 0; i < 4; ++i) {
        int s = t + i * 256, r = s >> 4, c4 = (s & 15) << 2;
        float4 vv = *reinterpret_cast<const float4*>(B + (long long)r * 64 + c4);
        uint2 u = make_uint2(pack2(vv.x, vv.y), pack2(vv.z, vv.w));
        *reinterpret_cast<uint2*>(&Bs[r * 36 + (c4 >> 1)]) = u;
    }
    __syncthreads();

    float acc[4][2][4];
#pragma unroll
    for (int i = 0; i < 4; ++i)
#pragma unroll
        for (int j = 0; j < 2; ++j)
#pragma unroll
            for (int e = 0; e < 4; ++e) acc[i][j][e] = 0.f;

#pragma unroll
    for (int ks = 0; ks < 4; ++ks) {
        int kb = ks * 8;
        uint32_t af[4][4];
#pragma unroll
        for (int mt = 0; mt < 4; ++mt) {
            int row = wm * 64 + mt * 16 + g;
            af[mt][0] = As[row * 36 + kb + tg];
            af[mt][1] = As[(row + 8) * 36 + kb + tg];
            af[mt][2] = As[row * 36 + kb + tg + 4];
            af[mt][3] = As[(row + 8) * 36 + kb + tg + 4];
        }
        uint32_t bf[2][2];
#pragma unroll
        for (int nt = 0; nt < 2; ++nt) {
            int col = wn * 16 + nt * 8 + g;
            bf[nt][0] = Bs[col * 36 + kb + tg];
            bf[nt][1] = Bs[col * 36 + kb + tg + 4];
        }
#pragma unroll
        for (int mt = 0; mt < 4; ++mt)
#pragma unroll
            for (int nt = 0; nt < 2; ++nt)
                mma16(acc[mt][nt], af[mt], bf[nt]);
    }

    uint32_t* Cw = reinterpret_cast<uint32_t*>(C) + (long long)blockIdx.x * 128 * 32;
#pragma unroll
    for (int mt = 0; mt < 4; ++mt) {
        int row = wm * 64 + mt * 16 + g;
#pragma unroll
        for (int nt = 0; nt < 2; ++nt) {
            int colw = (wn * 16 + nt * 8 + 2 * tg) >> 1;
            Cw[row * 32 + colw] =
                pack2(acc[mt][nt][0] * scale, acc[mt][nt][1] * scale);
            Cw[(row + 8) * 32 + colw] =
                pack2(acc[mt][nt][2] * scale, acc[mt][nt][3] * scale);
        }
    }
}

// ===========================================================================
// Big GEMM: out[8192 x 1024] = AO * Wt^T, fp16 in, fp32 out. 128x128 tile,
// k-chunk 64, cp.async TRIPLE buffer (single sync per chunk), ldmatrix,
// 2 CTAs/SM. smem words: As 3*4608 at 0; Bs 3*4608 at 13824. 110592 B.
// ===========================================================================
__global__ __launch_bounds__(256, 2) void gemm_big(
    const __half* __restrict__ A, const __half* __restrict__ B,
    float* __restrict__ C)
{
    extern __shared__ uint32_t sm[];
    const uint32_t sbase = smem_u32(sm);

    const int t = threadIdx.x, lane = t & 31, wid = t >> 5;
    const int wm = wid & 1, wn = wid >> 1;
    const int g = lane >> 2, tg = lane & 3;
    const int lA = laneA_off(lane), lB = laneB_off(lane);

    A += (long long)blockIdx.x * 128 * 1024;
    B += (long long)blockIdx.y * 128 * 1024;
    C += (long long)blockIdx.x * 128 * 1024 + (long long)blockIdx.y * 128;

    float acc[4][4][4];
#pragma unroll
    for (int i = 0; i < 4; ++i)
#pragma unroll
        for (int j = 0; j < 4; ++j)
#pragma unroll
            for (int e = 0; e < 4; ++e) acc[i][j][e] = 0.f;

#pragma unroll
    for (int i = 0; i < 4; ++i) {
        int s = t + i * 256, r = s >> 3, ch = s & 7;
        cp16(sbase + (r * 36 + ch * 4) * 4, A + (long long)r * 1024 + ch * 8);
        cp16(sbase + (13824 + r * 36 + ch * 4) * 4, B + (long long)r * 1024 + ch * 8);
    }
    CP_COMMIT();

    for (int ck = 0; ck < 16; ++ck) {
        if (ck < 15) {
            int kc = (ck + 1) * 64, b = (ck + 1) % 3;
#pragma unroll
            for (int i = 0; i < 4; ++i) {
                int s = t + i * 256, r = s >> 3, ch = s & 7;
                cp16(sbase + (b * 4608 + r * 36 + ch * 4) * 4,
                     A + (long long)r * 1024 + kc + ch * 8);
                cp16(sbase + (13824 + b * 4608 + r * 36 + ch * 4) * 4,
                     B + (long long)r * 1024 + kc + ch * 8);
            }
            CP_COMMIT();
            CP_WAIT(1);
        } else {
            CP_WAIT(0);
        }
        __syncthreads();   // single barrier per chunk (triple buffer)

        const int rb = ck % 3;
        const uint32_t Aad = sbase + (rb * 4608 + wm * 64 * 36 + lA) * 4;
        const uint32_t Bad = sbase + (13824 + rb * 4608 + wn * 32 * 36 + lB) * 4;
#pragma unroll
        for (int ks = 0; ks < 4; ++ks) {
            uint32_t af[4][4];
#pragma unroll
            for (int mt = 0; mt < 4; ++mt)
                ldsm4(af[mt], Aad + (mt * 16 * 36 + ks * 8) * 4);
            uint32_t bfp[2][4];
#pragma unroll
            for (int ntp = 0; ntp < 2; ++ntp)
                ldsm4(bfp[ntp], Bad + (ntp * 16 * 36 + ks * 8) * 4);
#pragma unroll
            for (int mt = 0; mt < 4; ++mt)
#pragma unroll
                for (int ntp = 0; ntp < 2; ++ntp) {
                    mma16(acc[mt][2 * ntp],     af[mt], &bfp[ntp][0]);
                    mma16(acc[mt][2 * ntp + 1], af[mt], &bfp[ntp][2]);
                }
        }
    }

#pragma unroll
    for (int mt = 0; mt < 4; ++mt) {
        int row = wm * 64 + mt * 16 + g;
#pragma unroll
        for (int nt = 0; nt < 4; ++nt) {
            int col = wn * 32 + nt * 8 + 2 * tg;
            *reinterpret_cast<float2*>(C + (long long)row * 1024 + col) =
                make_float2(acc[mt][nt][0], acc[mt][nt][1]);
            *reinterpret_cast<float2*>(C + (long long)(row + 8) * 1024 + col) =
                make_float2(acc[mt][nt][2], acc[mt][nt][3]);
        }
    }
}

// ===========================================================================
// Flash attention, fp16 mma m16n8k16, BK=64 TRIPLE-buffered, 2 CTAs/SM.
// 8 warps x 16 q-rows. Q pre-scaled by log2(e)/32 -> exp path is pack+ex2
// only. S/exp/PV fused per 16-col slice. smem words: Qs 0 (4608),
// K bufs 4608 + b*2304 (x3), V bufs 11520 + b*2304 (x3). 73728 B.
// ===========================================================================
__global__ __launch_bounds__(256, 2) void attn_tc(
    const __half* __restrict__ Qp, const __half* __restrict__ Kp,
    const __half* __restrict__ Vp, __half* __restrict__ AO)
{
    extern __shared__ uint32_t sm[];
    const uint32_t sbase = smem_u32(sm);

    const int t = threadIdx.x, lane = t & 31, wid = t >> 5;
    const int g = lane >> 2, tg = lane & 3;
    const int lA = laneA_off(lane), lB = laneB_off(lane);
    const int qt = blockIdx.x, h = blockIdx.y, n = blockIdx.z;

    const long long base = ((long long)n << 20) + h * 64;          // halves
    const __half* Qb = Qp + base + (long long)(qt * 128) * 1024;

    // prefetch Q [128r x 32w] + K/V tile0 into buf0 (group 0)
#pragma unroll
    for (int i = 0; i < 4; ++i) {
        int s = t + i * 256, r = s >> 3, ch = s & 7;
        cp16(sbase + (r * 36 + ch * 4) * 4, Qb + (long long)r * 1024 + ch * 8);
    }
#pragma unroll
    for (int i = 0; i < 2; ++i) {
        int s = t + i * 256, r = s >> 3, ch = s & 7;
        cp16(sbase + (4608 + r * 36 + ch * 4) * 4, Kp + base + (long long)r * 1024 + ch * 8);
        cp16(sbase + (11520 + r * 36 + ch * 4) * 4, Vp + base + (long long)r * 1024 + ch * 8);
    }
    CP_COMMIT();

    float Of[8][4];
    float Osum[4] = {0.f, 0.f, 0.f, 0.f};
#pragma unroll
    for (int dtl = 0; dtl < 8; ++dtl)
#pragma unroll
        for (int e = 0; e < 4; ++e) Of[dtl][e] = 0.f;

    uint32_t Qa[4][4];                               // hoisted Q A-frags
    const uint32_t ONES2[2] = {0x3C003C00u, 0x3C003C00u};

    for (int kt = 0; kt < 16; ++kt) {
        if (kt < 15) {
            int b = (kt + 1) % 3;
            const __half* Kb = Kp + base + (long long)((kt + 1) * 64) * 1024;
            const __half* Vb = Vp + base + (long long)((kt + 1) * 64) * 1024;
#pragma unroll
            for (int i = 0; i < 2; ++i) {
                int s = t + i * 256, r = s >> 3, ch = s & 7;
                cp16(sbase + (4608 + b * 2304 + r * 36 + ch * 4) * 4,
                     Kb + (long long)r * 1024 + ch * 8);
                cp16(sbase + (11520 + b * 2304 + r * 36 + ch * 4) * 4,
                     Vb + (long long)r * 1024 + ch * 8);
            }
            CP_COMMIT();
            CP_WAIT(1);
        } else {
            CP_WAIT(0);
        }
        __syncthreads();   // single barrier per tile (triple buffer)

        if (kt == 0) {
            uint32_t Qad = sbase + (wid * 16 * 36 + lA) * 4;
#pragma unroll
            for (int ds = 0; ds < 4; ++ds)
                ldsm4(Qa[ds], Qad + ds * 8 * 4);
        }

        const int rb = kt % 3;
        const uint32_t Kad = sbase + (4608 + rb * 2304 + lB) * 4;
        const uint32_t Vad = sbase + (11520 + rb * 2304 + lA) * 4;

        // ---- fused per 16-col slice: S -> exp -> lsum-mma -> PV ----
#pragma unroll
        for (int ntp = 0; ntp < 4; ++ntp) {
            float Sa[4] = {0.f, 0.f, 0.f, 0.f};
            float Sb[4] = {0.f, 0.f, 0.f, 0.f};
#pragma unroll
            for (int ds = 0; ds < 4; ++ds) {
                uint32_t bf[4];
                ldsm4(bf, Kad + (ntp * 16 * 36 + ds * 8) * 4);
                mma16(Sa, Qa[ds], &bf[0]);
                mma16(Sb, Qa[ds], &bf[2]);
            }
            uint32_t pa[4];
            pa[0] = h2exp2w(pack2(Sa[0], Sa[1]));   // Q pre-scaled: no FMUL
            pa[1] = h2exp2w(pack2(Sa[2], Sa[3]));
            pa[2] = h2exp2w(pack2(Sb[0], Sb[1]));
            pa[3] = h2exp2w(pack2(Sb[2], Sb[3]));
            mma16(Osum, pa, ONES2);   // row-sums of P
#pragma unroll
            for (int dp = 0; dp < 4; ++dp) {
                uint32_t bf[4];
                ldsm4t(bf, Vad + (ntp * 16 * 36 + dp * 8) * 4);
                mma16(Of[2 * dp],     pa, &bf[0]);
                mma16(Of[2 * dp + 1], pa, &bf[2]);
            }
        }
    }

    // ---- epilogue: normalize (Osum c0 = row g, c2 = row g+8), write ----
    float inv0 = 1.f / Osum[0], inv1 = 1.f / Osum[2];

    const int q0 = qt * 128 + wid * 16 + g;
    uint32_t* Ob0 = reinterpret_cast<uint32_t*>(AO)
                  + (((long long)n * 1024 + q0) * 1024 + h * 64) / 2;
    uint32_t* Ob1 = reinterpret_cast<uint32_t*>(AO)
                  + (((long long)n * 1024 + q0 + 8) * 1024 + h * 64) / 2;
#pragma unroll
    for (int dtl = 0; dtl < 8; ++dtl) {
        int dw = (dtl * 8 + 2 * tg) >> 1;
        Ob0[dw] = pack2(Of[dtl][0] * inv0, Of[dtl][1] * inv0);
        Ob1[dw] = pack2(Of[dtl][2] * inv1, Of[dtl][3] * inv1);
    }
}

// ===========================================================================
extern "C" void kernel_launch(void* const* d_in, const int* in_sizes, int n_in,
                              void* d_out, int out_size)
{
    (void)in_sizes; (void)n_in; (void)out_size;
    const float* key   = (const float*)d_in[0];
    const float* query = (const float*)d_in[1];
    const float* value = (const float*)d_in[2];
    /* d_in[3] = mask — faithfully ignored (reference no-op) */
    const float* Wq = (const float*)d_in[4];
    const float* Wk = (const float*)d_in[5];
    const float* Wv = (const float*)d_in[6];
    const float* Wo = (const float*)d_in[7];
    float* out = (float*)d_out;

    __half *Qp, *Kp, *Vp, *AO, *Wt;
    cudaGetSymbolAddress((void**)&Qp, g_Qp);
    cudaGetSymbolAddress((void**)&Kp, g_Kp);
    cudaGetSymbolAddress((void**)&Vp, g_Vp);
    cudaGetSymbolAddress((void**)&AO, g_AO);
    cudaGetSymbolAddress((void**)&Wt, g_Wt);

    const int smem_proj = (128 * 36 + 64 * 36) * 4;   // 27648
    const int smem_big  = 27648 * 4;                  // 110592
    const int smem_attn = 18432 * 4;                  // 73728
    cudaFuncSetAttribute(proj_all,
        cudaFuncAttributeMaxDynamicSharedMemorySize, smem_proj);
    cudaFuncSetAttribute(gemm_big,
        cudaFuncAttributeMaxDynamicSharedMemorySize, smem_big);
    cudaFuncSetAttribute(attn_tc,
        cudaFuncAttributeMaxDynamicSharedMemorySize, smem_attn);

    dim3 blk(256);

    // Fused projections (y=0..2, 128-row tiles; Q pre-scaled) + Wo->fp16 (y=3)
    proj_all<<<dim3(1024, 4), blk, smem_proj>>>(
        query, key, value, Wq, Wk, Wv, Qp, Kp, Vp, Wo, Wt);

    // Attention: grid (q-tiles=8, heads=16, batch=8)
    attn_tc<<<dim3(8, NH, NB), blk, smem_attn>>>(Qp, Kp, Vp, AO);

    // Output projection: out = AO * Wt^T (fp16 in, fp32 out)
    gemm_big<<<dim3(64, 8), blk, smem_big>>>(AO, Wt, out);
}